// round 1
// baseline (speedup 1.0000x reference)
#include <cuda_runtime.h>
#include <math.h>

// One thread per box pair. Reproduces the JAX reference semantics:
//  - rad = atan2(sc0, sc1), but only cos/sin are consumed -> direct normalization
//  - 4x4 edge intersections with strict (0,1) t/u masks and den==0 -> t=-1
//  - box_in_box with eps=1e-6
//  - polygon area: stable sort of valid vertices by (angle, original index),
//    invalid keyed at +1e9 then padded with vs[0] => shoelace over sorted valid
//    vertices + closing edge. We implement this as an O(k^2) successor scan
//    over the COMPACTED valid set (compaction preserves original index order,
//    so tie-break by compact index == tie-break by original index).

__global__ void __launch_bounds__(256)
riou_kernel(const float* __restrict__ pred,
            const float* __restrict__ tgt,
            float* __restrict__ out, int n)
{
    int i = blockIdx.x * blockDim.x + threadIdx.x;
    if (i >= n) return;

    // ---- load (rows are 24B, 8B-aligned -> three float2 each) ----
    const float2* pp = reinterpret_cast<const float2*>(pred) + (size_t)i * 3;
    const float2* tp = reinterpret_cast<const float2*>(tgt)  + (size_t)i * 3;
    float2 a0 = pp[0], a1 = pp[1], a2 = pp[2];
    float2 b0 = tp[0], b1 = tp[1], b2 = tp[2];

    const float x1c = a0.x, y1c = a0.y, w1 = a1.x, h1 = a1.y;
    const float x2c = b0.x, y2c = b0.y, w2 = b1.x, h2 = b1.y;

    // cos/sin of atan2(sy, sx): c = sx/r, s = sy/r  (args: arctan2(pred[:,4], pred[:,5]))
    float inv1 = rsqrtf(a2.x * a2.x + a2.y * a2.y);
    float s1 = a2.x * inv1, c1 = a2.y * inv1;
    float inv2 = rsqrtf(b2.x * b2.x + b2.y * b2.y);
    float s2 = b2.x * inv2, c2 = b2.y * inv2;

    // ---- corners ----
    const float dxv[4] = {0.5f, -0.5f, -0.5f, 0.5f};
    const float dyv[4] = {0.5f, 0.5f, -0.5f, -0.5f};
    float c1x[4], c1y[4], c2x[4], c2y[4];
#pragma unroll
    for (int j = 0; j < 4; j++) {
        float cx = dxv[j] * w1, cy = dyv[j] * h1;
        c1x[j] = cx * c1 - cy * s1 + x1c;
        c1y[j] = cx * s1 + cy * c1 + y1c;
    }
#pragma unroll
    for (int j = 0; j < 4; j++) {
        float cx = dxv[j] * w2, cy = dyv[j] * h2;
        c2x[j] = cx * c2 - cy * s2 + x2c;
        c2y[j] = cx * s2 + cy * c2 + y2c;
    }

    // ---- collect valid candidate vertices (compacted, original order) ----
    float px[24], py[24];
    int   k = 0;
    float sumx = 0.f, sumy = 0.f;
    const float eps = 1e-6f;

    // corners of box1 inside box2
    {
        float ax = c2x[0], ay = c2y[0];
        float abx = c2x[1] - ax, aby = c2y[1] - ay;
        float adx = c2x[3] - ax, ady = c2y[3] - ay;
        float den_ab = abx * abx + aby * aby;
        float den_ad = adx * adx + ady * ady;
#pragma unroll
        for (int j = 0; j < 4; j++) {
            float amx = c1x[j] - ax, amy = c1y[j] - ay;
            float p_ab = (abx * amx + aby * amy) / den_ab;
            float p_ad = (adx * amx + ady * amy) / den_ad;
            if (p_ab > -eps && p_ab < 1.f + eps && p_ad > -eps && p_ad < 1.f + eps) {
                px[k] = c1x[j]; py[k] = c1y[j];
                sumx += c1x[j]; sumy += c1y[j];
                k++;
            }
        }
    }
    // corners of box2 inside box1
    {
        float ax = c1x[0], ay = c1y[0];
        float abx = c1x[1] - ax, aby = c1y[1] - ay;
        float adx = c1x[3] - ax, ady = c1y[3] - ay;
        float den_ab = abx * abx + aby * aby;
        float den_ad = adx * adx + ady * ady;
#pragma unroll
        for (int j = 0; j < 4; j++) {
            float amx = c2x[j] - ax, amy = c2y[j] - ay;
            float p_ab = (abx * amx + aby * amy) / den_ab;
            float p_ad = (adx * amx + ady * amy) / den_ad;
            if (p_ab > -eps && p_ab < 1.f + eps && p_ad > -eps && p_ad < 1.f + eps) {
                px[k] = c2x[j]; py[k] = c2y[j];
                sumx += c2x[j]; sumy += c2y[j];
                k++;
            }
        }
    }
    // 4x4 edge intersections (e1 outer, e2 inner to match reference flatten order)
#pragma unroll
    for (int e1 = 0; e1 < 4; e1++) {
        float X1 = c1x[e1], Y1 = c1y[e1];
        float X2 = c1x[(e1 + 1) & 3], Y2 = c1y[(e1 + 1) & 3];
        float ex = X2 - X1, ey = Y2 - Y1;
#pragma unroll
        for (int e2 = 0; e2 < 4; e2++) {
            float X3 = c2x[e2], Y3 = c2y[e2];
            float X4 = c2x[(e2 + 1) & 3], Y4 = c2y[(e2 + 1) & 3];
            float num_t = ex * (Y3 - Y1) - ey * (X3 - X1);
            float den_t = ex * (Y3 - Y4) - ey * (X3 - X4);
            float t = (den_t == 0.f) ? -1.f : num_t / den_t;
            float gx = X4 - X3, gy = Y4 - Y3;
            float num_u = gx * (Y1 - Y3) - gy * (X1 - X3);
            float den_u = gy * ex - gx * ey;   // gx*(Y1-Y2) - gy*(X1-X2) = -gx*ey + gy*ex
            float u = (den_u == 0.f) ? -1.f : num_u / den_u;
            if (t > 0.f && t < 1.f && u > 0.f && u < 1.f) {
                float ix = X1 + t * ex, iy = Y1 + t * ey;
                px[k] = ix; py[k] = iy;
                sumx += ix; sumy += iy;
                k++;
            }
        }
    }

    // ---- center + angles ----
    float kk = (float)(k > 0 ? k : 1);
    float meanx = sumx / kk, meany = sumy / kk;
    float ang[24];
    for (int j = 0; j < k; j++) {
        float vx = px[j] - meanx, vy = py[j] - meany;
        px[j] = vx; py[j] = vy;
        ang[j] = atan2f(vy, vx);
    }

    // ---- shoelace via successor-in-(angle,index)-order ----
    float cr = 0.f;
    for (int ii = 0; ii < k; ii++) {
        float ai = ang[ii];
        float bestA = INFINITY; int bestJ = -1;
        float minA  = INFINITY; int minJ  = 0;
        for (int jj = 0; jj < k; jj++) {
            float aj = ang[jj];
            if (aj < minA) { minA = aj; minJ = jj; }
            bool gt = (aj > ai) || (aj == ai && jj > ii);
            if (gt && aj < bestA) { bestA = aj; bestJ = jj; }
        }
        int s = (bestJ >= 0) ? bestJ : minJ;   // wrap to global min
        cr += px[ii] * py[s] - py[ii] * px[s];
    }
    float inter = 0.5f * fabsf(cr);

    // ---- enclosing box + loss ----
    float xmin = c1x[0], xmax = c1x[0], ymin = c1y[0], ymax = c1y[0];
#pragma unroll
    for (int j = 1; j < 4; j++) {
        xmin = fminf(xmin, c1x[j]); xmax = fmaxf(xmax, c1x[j]);
        ymin = fminf(ymin, c1y[j]); ymax = fmaxf(ymax, c1y[j]);
    }
#pragma unroll
    for (int j = 0; j < 4; j++) {
        xmin = fminf(xmin, c2x[j]); xmax = fmaxf(xmax, c2x[j]);
        ymin = fminf(ymin, c2y[j]); ymax = fmaxf(ymax, c2y[j]);
    }
    float wc = xmax - xmin, hc = ymax - ymin;
    float c2diag = wc * wc + hc * hc;
    float ddx = x1c - x2c, ddy = y1c - y2c;
    float d2 = ddx * ddx + ddy * ddy;

    float area1 = w1 * h1, area2 = w2 * h2;
    float uni = area1 + area2 - inter;
    out[i] = 1.0f - inter / uni + d2 / c2diag;
}

extern "C" void kernel_launch(void* const* d_in, const int* in_sizes, int n_in,
                              void* d_out, int out_size)
{
    const float* pred = (const float*)d_in[0];
    const float* tgt  = (const float*)d_in[1];
    float* out = (float*)d_out;
    int n = out_size;  // one loss per box pair
    int threads = 256;
    int blocks = (n + threads - 1) / threads;
    riou_kernel<<<blocks, threads>>>(pred, tgt, out, n);
}

// round 6
// speedup vs baseline: 1.3017x; 1.3017x over previous
#include <cuda_runtime.h>
#include <math.h>

// Rotated-IoU loss, one thread per pair. Exact replica of the reference's
// decision structure (round-1 kernel, passed at 4.96e-4), instruction-optimized:
//  - corner-in-box test: division replaced by multiply-compare (den > 0)
//  - t,u in (0,1) masks: pure sign/compare tests; division only for accepted hits
//  - atan2f replaced by monotone diamond pseudo-angle (order-preserving)
//  - global-min hoisted out of the O(k^2) successor scan; arrays 24 -> 16
// All replaced decisions differ from the reference only within ~ulp of mask
// boundaries, where the area effect is a sliver (or an exact duplicate point).

__device__ __forceinline__ float pseudo_angle(float x, float y)
{
    float d = fabsf(x) + fabsf(y);
    float r = __fdividef(y, d);
    r = (d > 0.f) ? r : 0.f;                 // guard v == (0,0)
    return (x >= 0.f) ? r : ((y >= 0.f) ? 2.f - r : -2.f - r);
}

__global__ void __launch_bounds__(256)
riou_kernel(const float* __restrict__ pred,
            const float* __restrict__ tgt,
            float* __restrict__ out, int n)
{
    int i = blockIdx.x * blockDim.x + threadIdx.x;
    if (i >= n) return;

    const float2* pp = reinterpret_cast<const float2*>(pred) + (size_t)i * 3;
    const float2* tp = reinterpret_cast<const float2*>(tgt)  + (size_t)i * 3;
    float2 a0 = pp[0], a1 = pp[1], a2 = pp[2];
    float2 b0 = tp[0], b1 = tp[1], b2 = tp[2];

    const float x1c = a0.x, y1c = a0.y, w1 = a1.x, h1 = a1.y;
    const float x2c = b0.x, y2c = b0.y, w2 = b1.x, h2 = b1.y;

    // cos/sin of atan2(s, c) via normalization (only cos/sin are consumed)
    float inv1 = rsqrtf(a2.x * a2.x + a2.y * a2.y);
    float s1 = a2.x * inv1, c1 = a2.y * inv1;
    float inv2 = rsqrtf(b2.x * b2.x + b2.y * b2.y);
    float s2 = b2.x * inv2, c2 = b2.y * inv2;

    const float dxv[4] = {0.5f, -0.5f, -0.5f, 0.5f};
    const float dyv[4] = {0.5f, 0.5f, -0.5f, -0.5f};
    float c1x[4], c1y[4], c2x[4], c2y[4];
#pragma unroll
    for (int j = 0; j < 4; j++) {
        float cx = dxv[j] * w1, cy = dyv[j] * h1;
        c1x[j] = cx * c1 - cy * s1 + x1c;
        c1y[j] = cx * s1 + cy * c1 + y1c;
    }
#pragma unroll
    for (int j = 0; j < 4; j++) {
        float cx = dxv[j] * w2, cy = dyv[j] * h2;
        c2x[j] = cx * c2 - cy * s2 + x2c;
        c2y[j] = cx * s2 + cy * c2 + y2c;
    }

    // ---- gather valid candidate vertices (compacted, reference order) ----
    float px[16], py[16];
    int   k = 0;
    float sumx = 0.f, sumy = 0.f;
    const float eps = 1e-6f;

    // corners of box1 inside box2 (division-free: den_ab, den_ad > 0)
    {
        float ax = c2x[0], ay = c2y[0];
        float abx = c2x[1] - ax, aby = c2y[1] - ay;
        float adx = c2x[3] - ax, ady = c2y[3] - ay;
        float den_ab = abx * abx + aby * aby;
        float den_ad = adx * adx + ady * ady;
        float lo_ab = -eps * den_ab, hi_ab = (1.f + eps) * den_ab;
        float lo_ad = -eps * den_ad, hi_ad = (1.f + eps) * den_ad;
#pragma unroll
        for (int j = 0; j < 4; j++) {
            float amx = c1x[j] - ax, amy = c1y[j] - ay;
            float d_ab = abx * amx + aby * amy;
            float d_ad = adx * amx + ady * amy;
            if (d_ab > lo_ab && d_ab < hi_ab && d_ad > lo_ad && d_ad < hi_ad) {
                px[k] = c1x[j]; py[k] = c1y[j];
                sumx += c1x[j]; sumy += c1y[j];
                k++;
            }
        }
    }
    // corners of box2 inside box1
    {
        float ax = c1x[0], ay = c1y[0];
        float abx = c1x[1] - ax, aby = c1y[1] - ay;
        float adx = c1x[3] - ax, ady = c1y[3] - ay;
        float den_ab = abx * abx + aby * aby;
        float den_ad = adx * adx + ady * ady;
        float lo_ab = -eps * den_ab, hi_ab = (1.f + eps) * den_ab;
        float lo_ad = -eps * den_ad, hi_ad = (1.f + eps) * den_ad;
#pragma unroll
        for (int j = 0; j < 4; j++) {
            float amx = c2x[j] - ax, amy = c2y[j] - ay;
            float d_ab = abx * amx + aby * amy;
            float d_ad = adx * amx + ady * amy;
            if (d_ab > lo_ab && d_ab < hi_ab && d_ad > lo_ad && d_ad < hi_ad) {
                px[k] = c2x[j]; py[k] = c2y[j];
                sumx += c2x[j]; sumy += c2y[j];
                k++;
            }
        }
    }
    // 4x4 edge intersections; masks are sign tests, division only on accept.
    // t in (0,1): den>0 ? 0<num<den : (den<0 && den<num<0). Same for u with
    // den_u = -den (exact-math identity with the reference's den_u).
#pragma unroll
    for (int e1 = 0; e1 < 4; e1++) {
        float X1 = c1x[e1], Y1 = c1y[e1];
        float X2 = c1x[(e1 + 1) & 3], Y2 = c1y[(e1 + 1) & 3];
        float ex = X2 - X1, ey = Y2 - Y1;
#pragma unroll
        for (int e2 = 0; e2 < 4; e2++) {
            float X3 = c2x[e2], Y3 = c2y[e2];
            float X4 = c2x[(e2 + 1) & 3], Y4 = c2y[(e2 + 1) & 3];
            float gx = X4 - X3, gy = Y4 - Y3;
            float num_t = ex * (Y3 - Y1) - ey * (X3 - X1);
            float den   = ex * (Y3 - Y4) - ey * (X3 - X4);
            float num_u = gx * (Y1 - Y3) - gy * (X1 - X3);
            float den_u = -den;
            bool vt = (den > 0.f) ? (num_t > 0.f && num_t < den)
                                  : (den < 0.f && num_t < 0.f && num_t > den);
            bool vu = (den_u > 0.f) ? (num_u > 0.f && num_u < den_u)
                                    : (den_u < 0.f && num_u < 0.f && num_u > den_u);
            if (vt && vu) {
                float t = __fdividef(num_t, den);
                float ix = X1 + t * ex, iy = Y1 + t * ey;
                px[k] = ix; py[k] = iy;
                sumx += ix; sumy += iy;
                k++;
            }
        }
    }

    // ---- center + pseudo-angles ----
    float invk = __fdividef(1.f, (float)(k > 0 ? k : 1));
    float meanx = sumx * invk, meany = sumy * invk;
    float ang[16];
    for (int j = 0; j < k; j++) {
        float vx = px[j] - meanx, vy = py[j] - meany;
        px[j] = vx; py[j] = vy;
        ang[j] = pseudo_angle(vx, vy);
    }

    // ---- shoelace via successor-in-(key,index)-order, min hoisted ----
    float minA = 1e30f; int minJ = 0;
    for (int j = 0; j < k; j++) {
        float aj = ang[j];
        if (aj < minA) { minA = aj; minJ = j; }
    }
    float cr = 0.f;
    for (int ii = 0; ii < k; ii++) {
        float ai = ang[ii];
        float bestA = 1e30f; int bestJ = minJ;   // wrap to global min
        for (int jj = 0; jj < k; jj++) {
            float aj = ang[jj];
            bool gt = (aj > ai) || (aj == ai && jj > ii);
            if (gt && aj < bestA) { bestA = aj; bestJ = jj; }
        }
        cr += px[ii] * py[bestJ] - py[ii] * px[bestJ];
    }
    float inter = 0.5f * fabsf(cr);

    // ---- enclosing box + loss ----
    float xmin = c1x[0], xmax = c1x[0], ymin = c1y[0], ymax = c1y[0];
#pragma unroll
    for (int j = 1; j < 4; j++) {
        xmin = fminf(xmin, c1x[j]); xmax = fmaxf(xmax, c1x[j]);
        ymin = fminf(ymin, c1y[j]); ymax = fmaxf(ymax, c1y[j]);
    }
#pragma unroll
    for (int j = 0; j < 4; j++) {
        xmin = fminf(xmin, c2x[j]); xmax = fmaxf(xmax, c2x[j]);
        ymin = fminf(ymin, c2y[j]); ymax = fmaxf(ymax, c2y[j]);
    }
    float wc = xmax - xmin, hc = ymax - ymin;
    float c2diag = wc * wc + hc * hc;
    float ddx = x1c - x2c, ddy = y1c - y2c;
    float d2 = ddx * ddx + ddy * ddy;

    float area1 = w1 * h1, area2 = w2 * h2;
    float uni = area1 + area2 - inter;
    out[i] = 1.0f - __fdividef(inter, uni) + __fdividef(d2, c2diag);
}

extern "C" void kernel_launch(void* const* d_in, const int* in_sizes, int n_in,
                              void* d_out, int out_size)
{
    const float* pred = (const float*)d_in[0];
    const float* tgt  = (const float*)d_in[1];
    float* out = (float*)d_out;
    int n = out_size;
    int threads = 256;
    int blocks = (n + threads - 1) / threads;
    riou_kernel<<<blocks, threads>>>(pred, tgt, out, n);
}

// round 7
// speedup vs baseline: 1.4336x; 1.1014x over previous
#include <cuda_runtime.h>
#include <math.h>

// Rotated-IoU loss, one thread per pair. Reference decision structure
// (rounds 1/6, rel_err 4.96e-4) with the O(k^2) successor-search replaced by
// rank-counting (independent predicate sums, full ILP) + scatter to sorted
// slots + a fixed unrolled shoelace. Summation order of the cross terms is
// identical to the reference's sorted order (starts at the global angle min),
// so rounding behavior matches as well.

__device__ __forceinline__ float pseudo_angle(float x, float y)
{
    float d = fabsf(x) + fabsf(y);
    float r = __fdividef(y, d);
    r = (d > 0.f) ? r : 0.f;                 // guard v == (0,0)
    return (x >= 0.f) ? r : ((y >= 0.f) ? 2.f - r : -2.f - r);
}

__global__ void __launch_bounds__(256)
riou_kernel(const float* __restrict__ pred,
            const float* __restrict__ tgt,
            float* __restrict__ out, int n)
{
    int i = blockIdx.x * blockDim.x + threadIdx.x;
    if (i >= n) return;

    const float2* pp = reinterpret_cast<const float2*>(pred) + (size_t)i * 3;
    const float2* tp = reinterpret_cast<const float2*>(tgt)  + (size_t)i * 3;
    float2 a0 = pp[0], a1 = pp[1], a2 = pp[2];
    float2 b0 = tp[0], b1 = tp[1], b2 = tp[2];

    const float x1c = a0.x, y1c = a0.y, w1 = a1.x, h1 = a1.y;
    const float x2c = b0.x, y2c = b0.y, w2 = b1.x, h2 = b1.y;

    float inv1 = rsqrtf(a2.x * a2.x + a2.y * a2.y);
    float s1 = a2.x * inv1, c1 = a2.y * inv1;
    float inv2 = rsqrtf(b2.x * b2.x + b2.y * b2.y);
    float s2 = b2.x * inv2, c2 = b2.y * inv2;

    const float dxv[4] = {0.5f, -0.5f, -0.5f, 0.5f};
    const float dyv[4] = {0.5f, 0.5f, -0.5f, -0.5f};
    float c1x[4], c1y[4], c2x[4], c2y[4];
#pragma unroll
    for (int j = 0; j < 4; j++) {
        float cx = dxv[j] * w1, cy = dyv[j] * h1;
        c1x[j] = cx * c1 - cy * s1 + x1c;
        c1y[j] = cx * s1 + cy * c1 + y1c;
    }
#pragma unroll
    for (int j = 0; j < 4; j++) {
        float cx = dxv[j] * w2, cy = dyv[j] * h2;
        c2x[j] = cx * c2 - cy * s2 + x2c;
        c2y[j] = cx * s2 + cy * c2 + y2c;
    }

    // ---- gather valid candidate vertices (compacted, reference order) ----
    float2 v[16];
    int    k = 0;
    float  sumx = 0.f, sumy = 0.f;
    const float eps = 1e-6f;

    // corners of box1 inside box2 (division-free: denominators > 0)
    {
        float ax = c2x[0], ay = c2y[0];
        float abx = c2x[1] - ax, aby = c2y[1] - ay;
        float adx = c2x[3] - ax, ady = c2y[3] - ay;
        float den_ab = abx * abx + aby * aby;
        float den_ad = adx * adx + ady * ady;
        float lo_ab = -eps * den_ab, hi_ab = (1.f + eps) * den_ab;
        float lo_ad = -eps * den_ad, hi_ad = (1.f + eps) * den_ad;
#pragma unroll
        for (int j = 0; j < 4; j++) {
            float amx = c1x[j] - ax, amy = c1y[j] - ay;
            float d_ab = abx * amx + aby * amy;
            float d_ad = adx * amx + ady * amy;
            if (d_ab > lo_ab && d_ab < hi_ab && d_ad > lo_ad && d_ad < hi_ad) {
                v[k] = make_float2(c1x[j], c1y[j]);
                sumx += c1x[j]; sumy += c1y[j];
                k++;
            }
        }
    }
    // corners of box2 inside box1
    {
        float ax = c1x[0], ay = c1y[0];
        float abx = c1x[1] - ax, aby = c1y[1] - ay;
        float adx = c1x[3] - ax, ady = c1y[3] - ay;
        float den_ab = abx * abx + aby * aby;
        float den_ad = adx * adx + ady * ady;
        float lo_ab = -eps * den_ab, hi_ab = (1.f + eps) * den_ab;
        float lo_ad = -eps * den_ad, hi_ad = (1.f + eps) * den_ad;
#pragma unroll
        for (int j = 0; j < 4; j++) {
            float amx = c2x[j] - ax, amy = c2y[j] - ay;
            float d_ab = abx * amx + aby * amy;
            float d_ad = adx * amx + ady * amy;
            if (d_ab > lo_ab && d_ab < hi_ab && d_ad > lo_ad && d_ad < hi_ad) {
                v[k] = make_float2(c2x[j], c2y[j]);
                sumx += c2x[j]; sumy += c2y[j];
                k++;
            }
        }
    }
    // 4x4 edge intersections; masks are sign tests, division only on accept
#pragma unroll
    for (int e1 = 0; e1 < 4; e1++) {
        float X1 = c1x[e1], Y1 = c1y[e1];
        float X2 = c1x[(e1 + 1) & 3], Y2 = c1y[(e1 + 1) & 3];
        float ex = X2 - X1, ey = Y2 - Y1;
#pragma unroll
        for (int e2 = 0; e2 < 4; e2++) {
            float X3 = c2x[e2], Y3 = c2y[e2];
            float X4 = c2x[(e2 + 1) & 3], Y4 = c2y[(e2 + 1) & 3];
            float gx = X4 - X3, gy = Y4 - Y3;
            float num_t = ex * (Y3 - Y1) - ey * (X3 - X1);
            float den   = ex * (Y3 - Y4) - ey * (X3 - X4);
            float num_u = gx * (Y1 - Y3) - gy * (X1 - X3);
            float den_u = -den;
            bool vt = (den > 0.f) ? (num_t > 0.f && num_t < den)
                                  : (den < 0.f && num_t < 0.f && num_t > den);
            bool vu = (den_u > 0.f) ? (num_u > 0.f && num_u < den_u)
                                    : (den_u < 0.f && num_u < 0.f && num_u > den_u);
            if (vt && vu) {
                float t = __fdividef(num_t, den);
                float ix = X1 + t * ex, iy = Y1 + t * ey;
                v[k] = make_float2(ix, iy);
                sumx += ix; sumy += iy;
                k++;
            }
        }
    }

    // ---- center + pseudo-angles (in place) ----
    float invk = __fdividef(1.f, (float)(k > 0 ? k : 1));
    float meanx = sumx * invk, meany = sumy * invk;
    float ang[16];
    for (int j = 0; j < k; j++) {
        float vx = v[j].x - meanx, vy = v[j].y - meany;
        v[j] = make_float2(vx, vy);
        ang[j] = pseudo_angle(vx, vy);
    }

    // ---- rank-count (independent predicates, no dependent min-chain) ----
    float2 s[16];
    for (int ii = 0; ii < k; ii++) {
        float ai = ang[ii];
        int r = 0;
        for (int jj = 0; jj < k; jj++) {
            float aj = ang[jj];
            r += (int)((aj < ai) || (aj == ai && jj < ii));
        }
        s[r] = v[ii];
    }

    // ---- fixed unrolled shoelace over sorted slots + wrap term ----
    float cr = 0.f;
#pragma unroll
    for (int j = 0; j < 15; j++) {
        if (j + 1 < k) {
            float2 a = s[j], b = s[j + 1];
            cr += a.x * b.y - a.y * b.x;
        }
    }
    if (k > 0) {
        float2 l = s[k - 1], f = s[0];
        cr += l.x * f.y - l.y * f.x;
    }
    float inter = 0.5f * fabsf(cr);

    // ---- enclosing box + loss ----
    float xmin = c1x[0], xmax = c1x[0], ymin = c1y[0], ymax = c1y[0];
#pragma unroll
    for (int j = 1; j < 4; j++) {
        xmin = fminf(xmin, c1x[j]); xmax = fmaxf(xmax, c1x[j]);
        ymin = fminf(ymin, c1y[j]); ymax = fmaxf(ymax, c1y[j]);
    }
#pragma unroll
    for (int j = 0; j < 4; j++) {
        xmin = fminf(xmin, c2x[j]); xmax = fmaxf(xmax, c2x[j]);
        ymin = fminf(ymin, c2y[j]); ymax = fmaxf(ymax, c2y[j]);
    }
    float wc = xmax - xmin, hc = ymax - ymin;
    float c2diag = wc * wc + hc * hc;
    float ddx = x1c - x2c, ddy = y1c - y2c;
    float d2 = ddx * ddx + ddy * ddy;

    float area1 = w1 * h1, area2 = w2 * h2;
    float uni = area1 + area2 - inter;
    out[i] = 1.0f - __fdividef(inter, uni) + __fdividef(d2, c2diag);
}

extern "C" void kernel_launch(void* const* d_in, const int* in_sizes, int n_in,
                              void* d_out, int out_size)
{
    const float* pred = (const float*)d_in[0];
    const float* tgt  = (const float*)d_in[1];
    float* out = (float*)d_out;
    int n = out_size;
    int threads = 256;
    int blocks = (n + threads - 1) / threads;
    riou_kernel<<<blocks, threads>>>(pred, tgt, out, n);
}